// round 12
// baseline (speedup 1.0000x reference)
#include <cuda_runtime.h>

#define NCLS 200
#define NP   10
#define D    512
#define D4   128        // D / 4 (float4 granules)
#define NTOK 8192
#define ITERS 5
#define EPSF 0.01f
#define MAXC 128        // max tokens/class: binomial(8192,1/200) mean 41, sd 6.4 -> +13.6 sigma

// ---------------- device scratch (no allocations allowed) ----------------
__device__ int   g_counts[NCLS];
__device__ int   g_offsets[NCLS];
__device__ int   g_tokidx[NTOK];
__device__ float g_W[NCLS * MAXC * NP];   // fused final weights (pi_/colsum * inv_norm)
__device__ int   g_is64;

__device__ __forceinline__ float warpsum(float x) {
    #pragma unroll
    for (int o = 16; o; o >>= 1) x += __shfl_xor_sync(0xffffffff, x, o);
    return x;
}
__device__ __forceinline__ float dot4(float4 a, float4 b) {
    return a.x * b.x + a.y * b.y + a.z * b.z + a.w * b.w;
}

// ---------------- k1: fused probe + histogram + scan + scatter (1 block) ----------------
__global__ void __launch_bounds__(1024) k_prep(const int* __restrict__ labels) {
    __shared__ int scnt[NCLS];     // histogram, then cursors
    __shared__ int ssum[256];      // inclusive scan
    __shared__ int s_is64;
    int t = threadIdx.x;
    if (t == 0) {
        // int64 LE labels in [0,200): every odd 32-bit word of the first 32
        // entries is 0 and every even word in range. For genuine int32 labels
        // the odds of passing are ~(1/200)^32 — safe probe.
        int is64 = 1;
        for (int i = 0; i < 32; i++) {
            int lo = labels[2 * i], hi = labels[2 * i + 1];
            if (hi != 0 || lo < 0 || lo >= NCLS) { is64 = 0; break; }
        }
        s_is64 = is64;
        g_is64 = is64;
    }
    for (int i = t; i < NCLS; i += 1024) scnt[i] = 0;
    __syncthreads();
    int is64 = s_is64;
    int lab[8];
    #pragma unroll
    for (int k = 0; k < 8; k++) {
        int n = t + 1024 * k;
        lab[k] = is64 ? labels[2 * n] : labels[n];
        atomicAdd(&scnt[lab[k]], 1);
    }
    __syncthreads();
    int v = 0;
    if (t < 256) { v = (t < NCLS) ? scnt[t] : 0; ssum[t] = v; }
    __syncthreads();
    #pragma unroll
    for (int o = 1; o < 256; o <<= 1) {
        int add = 0;
        if (t < 256 && t >= o) add = ssum[t - o];
        __syncthreads();
        if (t < 256) ssum[t] += add;
        __syncthreads();
    }
    if (t < NCLS) {
        g_counts[t] = v;
        int off = ssum[t] - v;      // exclusive
        g_offsets[t] = off;
        scnt[t] = off;              // reuse as cursor
    }
    __syncthreads();
    #pragma unroll
    for (int k = 0; k < 8; k++) {
        int pos = atomicAdd(&scnt[lab[k]], 1);
        g_tokidx[pos] = t + 1024 * k;   // order nondeterministic -> sorted in k_score
    }
}

// ---------------- k2: per-class scores + Sinkhorn -> weights (512 thr, 2 CTA/SM) ----------------
__global__ void __launch_bounds__(512, 2)
k_score(const float* __restrict__ tokens, const float* __restrict__ protos) {
    __shared__ float4 psh4[NP * D4];     // 20KB: class prototypes
    __shared__ float  Ssh[MAXC * NP];    // scores
    __shared__ float  vsh[MAXC];
    __shared__ float  insh[MAXC];
    __shared__ int    jsh[MAXC];
    __shared__ int    js2[MAXC];
    __shared__ float  ush[NP];

    int c = blockIdx.x;
    int t = threadIdx.x, w = t >> 5, lane = t & 31;
    int nc = g_counts[c];
    if (nc > MAXC) nc = MAXC;            // unreachable safety clamp
    int base = g_offsets[c];

    const float4* Pg = (const float4*)protos + (size_t)c * NP * D4;
    for (int i = t; i < NP * D4; i += 512) psh4[i] = Pg[i];
    for (int j = t; j < nc; j += 512) { jsh[j] = g_tokidx[base + j]; vsh[j] = 0.f; }
    if (t < NP) ush[t] = 0.f;
    __syncthreads();

    // parallel rank sort (keys unique) — deterministic token order
    if (t < nc) {
        int key = jsh[t], r = 0;
        for (int a = 0; a < nc; a++) r += (jsh[a] < key);
        js2[r] = key;
    }
    __syncthreads();
    if (t < nc) jsh[t] = js2[t];
    __syncthreads();

    // ---- S-pass: warp per token (16 warps -> <=3 rounds for nc<=~70) ----
    for (int j = w; j < nc; j += 16) {
        const float4* T = (const float4*)tokens + (size_t)jsh[j] * D4;
        float4 tv[4];
        #pragma unroll
        for (int q = 0; q < 4; q++) tv[q] = T[lane + 32 * q];
        float nn = 0.f;
        #pragma unroll
        for (int q = 0; q < 4; q++) nn += dot4(tv[q], tv[q]);
        float acc[NP];
        #pragma unroll
        for (int p = 0; p < NP; p++) acc[p] = 0.f;
        #pragma unroll
        for (int p = 0; p < NP; p++) {
            #pragma unroll
            for (int q = 0; q < 4; q++)
                acc[p] += dot4(psh4[p * D4 + lane + 32 * q], tv[q]);
        }
        nn = warpsum(nn);
        #pragma unroll
        for (int p = 0; p < NP; p++) acc[p] = warpsum(acc[p]);
        if (lane == 0) {
            float iv = 1.f / sqrtf(nn);
            insh[j] = iv;
            #pragma unroll
            for (int p = 0; p < NP; p++) Ssh[j * NP + p] = acc[p] * iv;
        }
    }
    __syncthreads();

    // ---- Sinkhorn (log-domain, reference u-then-v order) ----
    if (nc > 0) {
        const float invE = 1.0f / EPSF;
        const float log_a = logf(1.0f / (float)NP + 1e-8f);
        const float log_b = logf(1.0f / (float)nc + 1e-8f);
        for (int it = 0; it < ITERS; it++) {
            if (w < NP) {                      // warp w owns prototype row w
                float uold = ush[w];
                float m = -1e30f, s = 0.f;
                for (int j = lane; j < nc; j += 32)
                    m = fmaxf(m, Ssh[j * NP + w] + uold + vsh[j]);
                #pragma unroll
                for (int o = 16; o; o >>= 1) m = fmaxf(m, __shfl_xor_sync(0xffffffff, m, o));
                for (int j = lane; j < nc; j += 32)
                    s += expf((Ssh[j * NP + w] + uold + vsh[j] - m) * invE);
                s = warpsum(s);
                if (lane == 0) ush[w] = EPSF * (log_a - (m * invE + logf(s))) + uold;
            }
            __syncthreads();
            for (int j = t; j < nc; j += 512) {    // v update (new u, old v)
                float vold = vsh[j];
                float m2 = -1e30f;
                #pragma unroll
                for (int p = 0; p < NP; p++)
                    m2 = fmaxf(m2, Ssh[j * NP + p] + ush[p] + vold);
                float s2 = 0.f;
                #pragma unroll
                for (int p = 0; p < NP; p++)
                    s2 += expf((Ssh[j * NP + p] + ush[p] + vold - m2) * invE);
                vsh[j] = EPSF * (log_b - (m2 * invE + logf(s2))) + vold;
            }
            __syncthreads();
        }
        // ---- final plan, column-normalized, folded with token inv-norm ----
        for (int j = t; j < nc; j += 512) {
            float vj = vsh[j];
            float pi[NP], cs = 0.f;
            #pragma unroll
            for (int p = 0; p < NP; p++) {
                float e = expf((Ssh[j * NP + p] + ush[p] + vj) * invE);
                pi[p] = e; cs += e;
            }
            float f = insh[j] / cs;
            #pragma unroll
            for (int p = 0; p < NP; p++)
                g_W[((size_t)c * MAXC + j) * NP + p] = pi[p] * f;
            g_tokidx[base + j] = jsh[j];     // write back sorted (deterministic)
        }
    }
}

// ---------------- k3: per-class prototype update (gather, MLP-4, 3 CTA/SM) ----------------
__global__ void __launch_bounds__(256, 3)
k_update(const float* __restrict__ tokens, const float* __restrict__ protos,
         float* __restrict__ out) {
    __shared__ float  Wsh[MAXC * NP];    // 5KB weights
    __shared__ float4 psum[NP * D4];     // 20KB group-1 partials
    __shared__ int    jsh[MAXC];
    __shared__ float  red[4 * NP];
    __shared__ float  invp[NP];

    int c = blockIdx.x;
    int t = threadIdx.x, w = t >> 5, lane = t & 31;
    int nc = g_counts[c];
    if (nc > MAXC) nc = MAXC;
    int base = g_offsets[c];
    int gr = t >> 7;         // token group 0/1
    int gq = t & 127;        // float4 granule 0..127

    for (int j = t; j < nc; j += 256) jsh[j] = g_tokidx[base + j];
    for (int i = t; i < nc * NP; i += 256) Wsh[i] = g_W[(size_t)c * MAXC * NP + i];
    __syncthreads();

    float4 acc[NP];
    #pragma unroll
    for (int p = 0; p < NP; p++) acc[p] = make_float4(0.f, 0.f, 0.f, 0.f);

    // group gr handles j = gr, gr+2, ... ; unroll 4 -> 4 independent LDG.128 in flight
    int j = gr;
    for (; j + 6 < nc; j += 8) {
        const float4* T0 = (const float4*)tokens + (size_t)jsh[j]     * D4;
        const float4* T1 = (const float4*)tokens + (size_t)jsh[j + 2] * D4;
        const float4* T2 = (const float4*)tokens + (size_t)jsh[j + 4] * D4;
        const float4* T3 = (const float4*)tokens + (size_t)jsh[j + 6] * D4;
        float4 t0 = T0[gq], t1 = T1[gq], t2 = T2[gq], t3 = T3[gq];
        #pragma unroll
        for (int p = 0; p < NP; p++) {
            float w0 = Wsh[j * NP + p],       w1 = Wsh[(j + 2) * NP + p];
            float w2 = Wsh[(j + 4) * NP + p], w3 = Wsh[(j + 6) * NP + p];
            acc[p].x += w0 * t0.x + w1 * t1.x + w2 * t2.x + w3 * t3.x;
            acc[p].y += w0 * t0.y + w1 * t1.y + w2 * t2.y + w3 * t3.y;
            acc[p].z += w0 * t0.z + w1 * t1.z + w2 * t2.z + w3 * t3.z;
            acc[p].w += w0 * t0.w + w1 * t1.w + w2 * t2.w + w3 * t3.w;
        }
    }
    for (; j < nc; j += 2) {
        const float4* T = (const float4*)tokens + (size_t)jsh[j] * D4;
        float4 tv = T[gq];
        #pragma unroll
        for (int p = 0; p < NP; p++) {
            float wgt = Wsh[j * NP + p];
            acc[p].x += wgt * tv.x; acc[p].y += wgt * tv.y;
            acc[p].z += wgt * tv.z; acc[p].w += wgt * tv.w;
        }
    }
    __syncthreads();
    if (gr == 1) {
        #pragma unroll
        for (int p = 0; p < NP; p++) psum[p * D4 + gq] = acc[p];
    }
    __syncthreads();

    const float4* Pg = (const float4*)protos + (size_t)c * NP * D4;
    float4 z[NP];
    if (gr == 0) {                 // warps 0..3, lane = granule%32
        float ssq[NP];
        #pragma unroll
        for (int p = 0; p < NP; p++) {
            float4 o = psum[p * D4 + gq];
            float4 pv = Pg[p * D4 + gq];
            float4 zz;
            zz.x = 0.98f * pv.x + 0.02f * (acc[p].x + o.x);
            zz.y = 0.98f * pv.y + 0.02f * (acc[p].y + o.y);
            zz.z = 0.98f * pv.z + 0.02f * (acc[p].z + o.z);
            zz.w = 0.98f * pv.w + 0.02f * (acc[p].w + o.w);
            z[p] = zz;
            ssq[p] = dot4(zz, zz);
        }
        #pragma unroll
        for (int p = 0; p < NP; p++) {
            float s = warpsum(ssq[p]);
            if (lane == 0) red[w * NP + p] = s;
        }
    }
    __syncthreads();
    if (t < NP) {
        float s = red[t] + red[NP + t] + red[2 * NP + t] + red[3 * NP + t];
        invp[t] = 1.f / sqrtf(s);
    }
    __syncthreads();
    if (gr == 0) {
        float4* O = (float4*)out + (size_t)c * NP * D4;
        #pragma unroll
        for (int p = 0; p < NP; p++) {
            float iv = invp[p];
            float4 zz = z[p];
            zz.x *= iv; zz.y *= iv; zz.z *= iv; zz.w *= iv;
            O[p * D4 + gq] = zz;
        }
    }
}

// ---------------- launch ----------------
extern "C" void kernel_launch(void* const* d_in, const int* in_sizes, int n_in,
                              void* d_out, int out_size) {
    const float* tokens = (const float*)d_in[0];
    const int*   labels = (const int*)d_in[1];   // int32 or int64, probed on device
    const float* protos = (const float*)d_in[2];
    float* out = (float*)d_out;

    k_prep<<<1, 1024>>>(labels);
    k_score<<<NCLS, 512>>>(tokens, protos);
    k_update<<<NCLS, 256>>>(tokens, protos, out);
}